// round 16
// baseline (speedup 1.0000x reference)
#include <cuda_runtime.h>
#include <cuda_fp16.h>
#include <cstdint>
#include <math.h>

#define Bb    16
#define Nn    8192
#define F1    32
#define F2    32
#define KORD  5
#define M1    512
#define M2    128
#define W1C   32
#define W2C   512

#define K2      16384       // A storage K: [Ah | Al] fp16
#define KB2     8192        // X/T storage K: [Xh] fp16
#define BKB     64          // fp16 per k-stage (128B rows -> SW128)
#define MSTAGES 3
#define NKI     256         // 2*8192/64 logical k-stages (AhXh + AlXh)
#define KCH     4           // layer-2 split-K chunks (reverted from 8)
#define LKI     (NKI / KCH) // 64 = 21*3 + 1
#define KC1     8           // layer-1 split-K chunks
#define LKI1    (NKI / KC1) // 32

// ---------------- scratch ---------------------------------------------------
__device__ __half g_A3[(size_t)Nn * K2];
__device__ __half g_X3t[(size_t)W2C * KB2];
__device__ __half g_T3t[(size_t)W1C * KB2];
__device__ float g_T[5][Nn * W1C];
__device__ float g_Tp[KC1][Nn * W1C];
__device__ float g_U[5][(size_t)Nn * W2C];
__device__ float g_Up[KCH][(size_t)Nn * W2C];
__device__ float g_h[(size_t)Bb * Nn * F2];
__device__ float g_p[512 * Bb * M1];
__device__ float g_fc1[Bb * M1];
__device__ float g_fc2[Bb * M2];

// ---------------- PTX helpers (compute_103 BASELINE only) ------------------
__device__ __forceinline__ uint32_t smem_u32(const void* p) {
    uint32_t a;
    asm("{ .reg .u64 t; cvta.to.shared.u64 t, %1; cvt.u32.u64 %0, t; }" : "=r"(a) : "l"(p));
    return a;
}
#define CP_ASYNC16(dst, src) \
    asm volatile("cp.async.cg.shared.global [%0], [%1], 16;" :: "r"(dst), "l"(src) : "memory")
#define CP_COMMIT() asm volatile("cp.async.commit_group;" ::: "memory")
#define CP_WAIT1()  asm volatile("cp.async.wait_group 1;" ::: "memory")
#define LDSM4(r0, r1, r2, r3, addr) \
    asm volatile("ldmatrix.sync.aligned.m8n8.x4.shared.b16 {%0,%1,%2,%3}, [%4];" \
        : "=r"(r0), "=r"(r1), "=r"(r2), "=r"(r3) : "r"(addr))
#define MMA16816(d, a, b0, b1) \
    asm volatile("mma.sync.aligned.m16n8k16.row.col.f32.f16.f16.f32 " \
        "{%0,%1,%2,%3}, {%4,%5,%6,%7}, {%8,%9}, {%0,%1,%2,%3};" \
        : "+f"((d)[0]), "+f"((d)[1]), "+f"((d)[2]), "+f"((d)[3]) \
        : "r"((a)[0]), "r"((a)[1]), "r"((a)[2]), "r"((a)[3]), "r"(b0), "r"(b1))
#define SWZ(o) ((o) ^ (((o) >> 3) & 0x70u))

// k-stage j in [0,256): A chunk = j (Ah j<128 | Al j>=128); X chunk = j&127
__device__ __forceinline__ int mapA(int j) { return j; }
__device__ __forceinline__ int mapB(int j) { return j & 127; }

// ---------------- A split: A3 = [fp16(A) | fp16(A-Ah)] ---------------------
__global__ __launch_bounds__(256) void convert_a3(const float* __restrict__ A) {
    size_t idx = ((size_t)blockIdx.x * 256 + threadIdx.x) * 4;
    float4 v = *(const float4*)(A + idx);
    int n = (int)(idx >> 13);
    int m = (int)(idx & 8191);
    float f[4] = {v.x, v.y, v.z, v.w};
    __half h0 = __float2half_rn(f[0]), h1 = __float2half_rn(f[1]);
    __half h2 = __float2half_rn(f[2]), h3 = __float2half_rn(f[3]);
    __half l0 = __float2half_rn(f[0] - __half2float(h0));
    __half l1 = __float2half_rn(f[1] - __half2float(h1));
    __half l2 = __float2half_rn(f[2] - __half2float(h2));
    __half l3 = __float2half_rn(f[3] - __half2float(h3));
    size_t b = (size_t)n * K2 + m;
    *(__half2*)(g_A3 + b)            = __halves2half2(h0, h1);
    *(__half2*)(g_A3 + b + 2)        = __halves2half2(h2, h3);
    *(__half2*)(g_A3 + b + 8192)     = __halves2half2(l0, l1);
    *(__half2*)(g_A3 + b + 8192 + 2) = __halves2half2(l2, l3);
}

// ---------------- pack x[B,N,2] -> T0[N,32] --------------------------------
__global__ void pack_x_kernel(const float* __restrict__ x) {
    int idx = blockIdx.x * blockDim.x + threadIdx.x;
    if (idx >= Nn * W1C) return;
    int q = idx & 31, n = idx >> 5;
    g_T[0][idx] = x[((size_t)(q >> 1) * Nn + n) * 2 + (q & 1)];
}

// ---------------- T rounding+transpose: T[in][N,32] -> T3t[32, KB2] --------
__global__ __launch_bounds__(256) void split_t(int in_i) {
    __shared__ float t[32][33];
    const float* __restrict__ T = g_T[in_i];
    int tx = threadIdx.x & 31, ty = threadIdx.x >> 5;
    int k0 = blockIdx.x * 32;
    #pragma unroll
    for (int r = ty; r < 32; r += 8)
        t[r][tx] = T[(k0 + r) * W1C + tx];
    __syncthreads();
    #pragma unroll
    for (int r = ty; r < 32; r += 8)
        g_T3t[(size_t)r * KB2 + k0 + tx] = __float2half_rn(t[tx][r]);
}

// ---------------- X rounding+transpose (H1 only) ---------------------------
__global__ __launch_bounds__(256) void split_x(int in_i) {
    __shared__ float t[32][33];
    const float* __restrict__ U = g_U[in_i];
    int tx = threadIdx.x & 31, ty = threadIdx.x >> 5;
    int k0 = blockIdx.x * 32, n0 = blockIdx.y * 32;
    #pragma unroll
    for (int r = ty; r < 32; r += 8)
        t[r][tx] = U[(size_t)(k0 + r) * W2C + n0 + tx];
    __syncthreads();
    #pragma unroll
    for (int r = ty; r < 32; r += 8)
        g_X3t[(size_t)(n0 + r) * KB2 + k0 + tx] = __float2half_rn(t[tx][r]);
}

// ---------------- layer-1 tensor GEMM: partial(A3@T3t^T) -> g_Tp[kc] -------
// Tile 128x32, BK=64, 8 warps (4M x 2N), warp tile 32x16 = 2x2 m16n8k16.
#define SM1_STG 20480
__global__ __launch_bounds__(256, 3) void gemm_mma32() {
    extern __shared__ char dsm[];
    uint32_t tiles = (smem_u32(dsm) + 1023u) & ~1023u;
    const int tid  = threadIdx.x;
    const int lane = tid & 31, warp = tid >> 5;
    const int brow = blockIdx.x * 128;
    const int kc   = blockIdx.y;
    const int j0   = kc * LKI1;
    const int wm = (warp >> 1) * 32, wn = (warp & 1) * 16;

    const int lrow = tid >> 1;
    const int c16  = (tid & 1) << 2;
    uint32_t swA[4];
    #pragma unroll
    for (int q = 0; q < 4; q++)
        swA[q] = SWZ((uint32_t)lrow * 128u + (uint32_t)(c16 + q) * 16u);
    const uint32_t swB = SWZ((uint32_t)(tid >> 3) * 128u + (uint32_t)(tid & 7) * 16u);
    const __half* gA0 = g_A3  + (size_t)(brow + lrow) * K2 + (c16 << 3);
    const __half* gB0 = g_T3t + (size_t)(tid >> 3) * KB2 + (tid & 7) * 8;

    auto load_stage = [&](int s, int j) {
        uint32_t sA = tiles + (uint32_t)s * SM1_STG;
        uint32_t sB = sA + 16384u;
        const __half* pa = gA0 + mapA(j) * BKB;
        #pragma unroll
        for (int q = 0; q < 4; q++)
            CP_ASYNC16(sA + swA[q], pa + q * 8);
        CP_ASYNC16(sB + swB, gB0 + mapB(j) * BKB);
    };

    const int ar        = wm + (lane & 15);
    const uint32_t aMsk = (uint32_t)(ar & 7) << 4;
    const uint32_t aKhi = (uint32_t)((lane >> 4) << 4);
    const int br        = wn + (lane & 7) + ((lane >> 4) & 1) * 8;
    const uint32_t bMsk = (uint32_t)(lane & 7) << 4;
    const uint32_t bKhi = (uint32_t)(((lane >> 3) & 1) << 4);

    float acc[2][2][4];
    #pragma unroll
    for (int t = 0; t < 2; t++)
        #pragma unroll
        for (int u = 0; u < 2; u++)
            #pragma unroll
            for (int r = 0; r < 4; r++) acc[t][u][r] = 0.f;

    load_stage(0, j0); CP_COMMIT();
    load_stage(1, j0 + 1); CP_COMMIT();

    #define PROC1(s) do {                                                      \
        const int il = io + (s);                                               \
        CP_WAIT1();                                                            \
        __syncthreads();                                                       \
        if (il + 2 < LKI1) load_stage(((s) + 2) % MSTAGES, j0 + il + 2);       \
        CP_COMMIT();                                                           \
        const uint32_t As = tiles + (uint32_t)(s) * SM1_STG;                   \
        const uint32_t Bs = As + 16384u;                                       \
        _Pragma("unroll")                                                      \
        for (int ks = 0; ks < 4; ks++) {                                       \
            uint32_t ka = (uint32_t)(ks * 32) + aKhi;                          \
            uint32_t kb = (uint32_t)(ks * 32) + bKhi;                          \
            uint32_t a[2][4], b[4];                                            \
            _Pragma("unroll")                                                  \
            for (int t = 0; t < 2; t++)                                        \
                LDSM4(a[t][0], a[t][1], a[t][2], a[t][3],                      \
                      As + (uint32_t)(ar + t * 16) * 128u + (ka ^ aMsk));      \
            LDSM4(b[0], b[1], b[2], b[3],                                      \
                  Bs + (uint32_t)br * 128u + (kb ^ bMsk));                     \
            _Pragma("unroll")                                                  \
            for (int t = 0; t < 2; t++) {                                      \
                MMA16816(acc[t][0], a[t], b[0], b[1]);                         \
                MMA16816(acc[t][1], a[t], b[2], b[3]);                         \
            }                                                                  \
        }                                                                      \
    } while (0)

    for (int io = 0; io < 30; io += 3) {
        PROC1(0);
        PROC1(1);
        PROC1(2);
    }
    { const int io = 30; PROC1(0); }
    { const int io = 30; PROC1(1); }
    #undef PROC1

    float* Po = g_Tp[kc];
    #pragma unroll
    for (int t = 0; t < 2; t++) {
        int r0 = brow + wm + t * 16 + (lane >> 2);
        #pragma unroll
        for (int u = 0; u < 2; u++) {
            int c0 = wn + u * 8 + (lane & 3) * 2;
            size_t o0 = (size_t)r0 * W1C + c0;
            size_t o1 = o0 + 8 * W1C;
            Po[o0]     = acc[t][u][0];
            Po[o0 + 1] = acc[t][u][1];
            Po[o1]     = acc[t][u][2];
            Po[o1 + 1] = acc[t][u][3];
        }
    }
}

// T[out] = alpha*sum(8 partials) + beta*T[prev]
__global__ __launch_bounds__(256) void w32_reduce8(int prev_i, int out_i,
                                                   float alpha, float beta) {
    size_t idx = ((size_t)blockIdx.x * 256 + threadIdx.x) * 4;
    float4 v = {0.f, 0.f, 0.f, 0.f};
    #pragma unroll
    for (int c = 0; c < KC1; c++) {
        float4 s = *(const float4*)(g_Tp[c] + idx);
        v.x += s.x; v.y += s.y; v.z += s.z; v.w += s.w;
    }
    v.x *= alpha; v.y *= alpha; v.z *= alpha; v.w *= alpha;
    if (prev_i >= 0) {
        float4 p = *(const float4*)(g_T[prev_i] + idx);
        v.x += beta * p.x; v.y += beta * p.y;
        v.z += beta * p.z; v.w += beta * p.w;
    }
    *(float4*)(g_T[out_i] + idx) = v;
}

// ---------------- layer-2 tensor GEMM v2: partial(A3@X3t^T) -> g_Up[kc] ----
// 128x128 tile, 4 warps (2x2), warp tile 64x64 = 4x8 m16n8k16, BK=64,
// 3-stage cp.async. Halves smem re-reads vs the 8-warp 64x32 version.
__global__ __launch_bounds__(128, 2) void gemm_mma() {
    extern __shared__ char dsm[];
    uint32_t tiles = (smem_u32(dsm) + 1023u) & ~1023u;
    const int tid  = threadIdx.x;
    const int lane = tid & 31, warp = tid >> 5;
    const int bcol = blockIdx.x * 128, brow = blockIdx.y * 128;
    const int kc   = blockIdx.z;
    const int j0   = kc * LKI;
    const int wm = (warp >> 1) * 64, wn = (warp & 1) * 64;

    // cp.async: 128 threads; A row = tid (8 chunks), B row = tid (8 chunks)
    uint32_t swoff[8];
    #pragma unroll
    for (int q = 0; q < 8; q++)
        swoff[q] = SWZ((uint32_t)tid * 128u + (uint32_t)q * 16u);
    const __half* gA0 = g_A3  + (size_t)(brow + tid) * K2;
    const __half* gB0 = g_X3t + (size_t)(bcol + tid) * KB2;

    auto load_stage = [&](int s, int j) {
        uint32_t sA = tiles + (uint32_t)s * 32768u;
        uint32_t sB = sA + 16384u;
        const __half* pa = gA0 + mapA(j) * BKB;
        const __half* pb = gB0 + mapB(j) * BKB;
        #pragma unroll
        for (int q = 0; q < 8; q++) {
            CP_ASYNC16(sA + swoff[q], pa + q * 8);
            CP_ASYNC16(sB + swoff[q], pb + q * 8);
        }
    };

    const int ar        = wm + (lane & 15);
    const uint32_t aMsk = (uint32_t)(ar & 7) << 4;
    const uint32_t aKhi = (uint32_t)((lane >> 4) << 4);
    const int br        = wn + (lane & 7) + ((lane >> 4) & 1) * 8;
    const uint32_t bMsk = (uint32_t)(lane & 7) << 4;
    const uint32_t bKhi = (uint32_t)(((lane >> 3) & 1) << 4);

    float acc[4][8][4];
    #pragma unroll
    for (int t = 0; t < 4; t++)
        #pragma unroll
        for (int u = 0; u < 8; u++)
            #pragma unroll
            for (int r = 0; r < 4; r++) acc[t][u][r] = 0.f;

    load_stage(0, j0); CP_COMMIT();
    load_stage(1, j0 + 1); CP_COMMIT();

    #define PROC_STAGE(s) do {                                                 \
        const int il = io + (s);                                               \
        CP_WAIT1();                                                            \
        __syncthreads();                                                       \
        if (il + 2 < LKI) load_stage(((s) + 2) % MSTAGES, j0 + il + 2);        \
        CP_COMMIT();                                                           \
        const uint32_t As = tiles + (uint32_t)(s) * 32768u;                    \
        const uint32_t Bs = As + 16384u;                                       \
        _Pragma("unroll")                                                      \
        for (int ks = 0; ks < 4; ks++) {                                       \
            uint32_t ka = (uint32_t)(ks * 32) + aKhi;                          \
            uint32_t kb = (uint32_t)(ks * 32) + bKhi;                          \
            uint32_t a[4][4], b[4][4];                                         \
            _Pragma("unroll")                                                  \
            for (int t = 0; t < 4; t++)                                        \
                LDSM4(a[t][0], a[t][1], a[t][2], a[t][3],                      \
                      As + (uint32_t)(ar + t * 16) * 128u + (ka ^ aMsk));      \
            _Pragma("unroll")                                                  \
            for (int p = 0; p < 4; p++)                                        \
                LDSM4(b[p][0], b[p][1], b[p][2], b[p][3],                      \
                      Bs + (uint32_t)(br + p * 16) * 128u + (kb ^ bMsk));      \
            _Pragma("unroll")                                                  \
            for (int t = 0; t < 4; t++) {                                      \
                _Pragma("unroll")                                              \
                for (int u = 0; u < 8; u++)                                    \
                    MMA16816(acc[t][u], a[t], b[u >> 1][(u & 1) * 2],          \
                                              b[u >> 1][(u & 1) * 2 + 1]);     \
            }                                                                  \
        }                                                                      \
    } while (0)

    // LKI = 64 = 21 triples (il 0..62) + il=63 (s=0)
    for (int io = 0; io < 63; io += 3) {
        PROC_STAGE(0);
        PROC_STAGE(1);
        PROC_STAGE(2);
    }
    { const int io = 63; PROC_STAGE(0); }
    #undef PROC_STAGE

    float* Po = g_Up[kc];
    #pragma unroll
    for (int t = 0; t < 4; t++) {
        int r0 = brow + wm + t * 16 + (lane >> 2);
        #pragma unroll
        for (int u = 0; u < 8; u++) {
            int c0 = bcol + wn + u * 8 + (lane & 3) * 2;
            size_t o0 = (size_t)r0 * W2C + c0;
            size_t o1 = o0 + 8 * W2C;
            Po[o0]     = acc[t][u][0];
            Po[o0 + 1] = acc[t][u][1];
            Po[o1]     = acc[t][u][2];
            Po[o1 + 1] = acc[t][u][3];
        }
    }
}

// ---------------- fused reduce (4 partials) + X split ----------------------
__global__ __launch_bounds__(256) void mma_reduce_split(int prev_i, int out_i,
                                                        float alpha, float beta,
                                                        int do_split) {
    __shared__ float t[32][33];
    const int tid = threadIdx.x;
    const int k0 = blockIdx.x * 32;      // U row (graph node) tile
    const int n0 = blockIdx.y * 32;      // U col tile
    const int r  = tid >> 3;             // 0..31
    const int c4 = (tid & 7) << 2;       // 0,4,..,28

    size_t idx = (size_t)(k0 + r) * W2C + n0 + c4;
    float4 s0 = *(const float4*)(g_Up[0] + idx);
    float4 s1 = *(const float4*)(g_Up[1] + idx);
    float4 s2 = *(const float4*)(g_Up[2] + idx);
    float4 s3 = *(const float4*)(g_Up[3] + idx);
    float4 v;
    v.x = alpha * (s0.x + s1.x + s2.x + s3.x);
    v.y = alpha * (s0.y + s1.y + s2.y + s3.y);
    v.z = alpha * (s0.z + s1.z + s2.z + s3.z);
    v.w = alpha * (s0.w + s1.w + s2.w + s3.w);
    if (prev_i >= 0) {
        float4 p = *(const float4*)(g_U[prev_i] + idx);
        v.x += beta * p.x; v.y += beta * p.y;
        v.z += beta * p.z; v.w += beta * p.w;
    }
    *(float4*)(g_U[out_i] + idx) = v;

    if (do_split) {
        t[r][c4 + 0] = v.x; t[r][c4 + 1] = v.y;
        t[r][c4 + 2] = v.z; t[r][c4 + 3] = v.w;
        __syncthreads();
        if (tid < 128) {
            int c  = tid >> 2;           // 0..31 (U col -> X3t row)
            int kk = (tid & 3) << 3;     // 0,8,16,24
            __half h[8];
            #pragma unroll
            for (int i = 0; i < 8; i++)
                h[i] = __float2half_rn(t[kk + i][c]);
            *(float4*)(g_X3t + (size_t)(n0 + c) * KB2 + k0 + kk) = *(float4*)h;
        }
    }
}

// ---------------- combines --------------------------------------------------
__global__ void combine1_kernel(const float* __restrict__ w1,
                                const float* __restrict__ b1) {
    int idx = blockIdx.x * blockDim.x + threadIdx.x;
    int c = idx & 31, b = (idx >> 5) & 15, n = idx >> 9;
    float v = b1[c];
    int tb = n * W1C + b * 2;
    #pragma unroll
    for (int k = 0; k < KORD; k++) {
        v = fmaf(g_T[k][tb + 0], w1[(k*2+0)*32 + c], v);
        v = fmaf(g_T[k][tb + 1], w1[(k*2+1)*32 + c], v);
    }
    g_U[0][(size_t)n * W2C + b * 32 + c] = fmaxf(v, 0.0f);
}

__global__ void combine2_kernel(const float* __restrict__ w2,
                                const float* __restrict__ b2) {
    int idx = blockIdx.x * blockDim.x + threadIdx.x;
    int c = idx & 31, b = (idx >> 5) & 15, n = idx >> 9;
    float v = b2[c];
    size_t ub = (size_t)n * W2C + b * 32;
    #pragma unroll
    for (int k = 0; k < KORD; k++)
        #pragma unroll
        for (int f = 0; f < F1; f++)
            v = fmaf(g_U[k][ub + f], w2[(k*F1 + f)*F2 + c], v);
    g_h[(size_t)b * (Nn * F2) + n * F2 + c] = fmaxf(v, 0.0f);
}

// ---------------- FC head ---------------------------------------------------
#define FC1_J 512
__global__ __launch_bounds__(256) void fc1_partial(const float* __restrict__ fw1) {
    __shared__ float hs[16][FC1_J];
    int tid = threadIdx.x;
    int j0  = blockIdx.x * FC1_J;
    for (int t = tid; t < 16 * FC1_J; t += 256)
        hs[t >> 9][t & (FC1_J - 1)] = g_h[(size_t)(t >> 9) * (Nn * F2) + j0 + (t & (FC1_J - 1))];
    __syncthreads();
    float acc0[16], acc1[16];
    #pragma unroll
    for (int b = 0; b < 16; b++) { acc0[b] = 0.f; acc1[b] = 0.f; }
    for (int jj = 0; jj < FC1_J; jj++) {
        float w0 = fw1[(size_t)(j0 + jj) * M1 + tid];
        float wA = fw1[(size_t)(j0 + jj) * M1 + tid + 256];
        #pragma unroll
        for (int b = 0; b < 16; b++) {
            float hv = hs[b][jj];
            acc0[b] = fmaf(hv, w0, acc0[b]);
            acc1[b] = fmaf(hv, wA, acc1[b]);
        }
    }
    size_t pb = (size_t)blockIdx.x * (16 * M1);
    #pragma unroll
    for (int b = 0; b < 16; b++) {
        g_p[pb + b * M1 + tid]       = acc0[b];
        g_p[pb + b * M1 + tid + 256] = acc1[b];
    }
}

__global__ void fc1_reduce(const float* __restrict__ fb1) {
    int idx = blockIdx.x * blockDim.x + threadIdx.x;
    float v = fb1[idx & (M1 - 1)];
    for (int ch = 0; ch < 512; ch++) v += g_p[(size_t)ch * (16 * M1) + idx];
    g_fc1[idx] = fmaxf(v, 0.0f);
}

__global__ void fc2_kernel(const float* __restrict__ fw2,
                           const float* __restrict__ fb2) {
    int idx = blockIdx.x * blockDim.x + threadIdx.x;
    int b = idx >> 7, m = idx & 127;
    float v = fb2[m];
    for (int j = 0; j < M1; j++)
        v = fmaf(g_fc1[b * M1 + j], fw2[j * M2 + m], v);
    g_fc2[idx] = fmaxf(v, 0.0f);
}

__global__ void fc3_kernel(const float* __restrict__ fw3,
                           const float* __restrict__ fb3,
                           float* __restrict__ out) {
    int b = threadIdx.x;
    if (b >= Bb) return;
    float l0 = fb3[0], l1 = fb3[1];
    for (int j = 0; j < M2; j++) {
        float h = g_fc2[b * M2 + j];
        l0 = fmaf(h, fw3[j * 2 + 0], l0);
        l1 = fmaf(h, fw3[j * 2 + 1], l1);
    }
    float mx = fmaxf(l0, l1);
    float e0 = expf(l0 - mx), e1 = expf(l1 - mx);
    float s = e0 + e1;
    out[b * 2 + 0] = e0 / s;
    out[b * 2 + 1] = e1 / s;
}

// ---------------- launcher -------------------------------------------------
#define MMA_SMEM  (MSTAGES * 32768 + 1024)
#define MMA1_SMEM (MSTAGES * SM1_STG + 1024)

extern "C" void kernel_launch(void* const* d_in, const int* in_sizes, int n_in,
                              void* d_out, int out_size) {
    const float* x   = (const float*)d_in[0];
    const float* a   = (const float*)d_in[1];
    const float* w1  = (const float*)d_in[2];
    const float* b1  = (const float*)d_in[3];
    const float* w2  = (const float*)d_in[4];
    const float* b2  = (const float*)d_in[5];
    const float* fw1 = (const float*)d_in[6];
    const float* fb1 = (const float*)d_in[7];
    const float* fw2 = (const float*)d_in[8];
    const float* fb2 = (const float*)d_in[9];
    const float* fw3 = (const float*)d_in[10];
    const float* fb3 = (const float*)d_in[11];
    float* out = (float*)d_out;

    cudaFuncSetAttribute(gemm_mma,   cudaFuncAttributeMaxDynamicSharedMemorySize, MMA_SMEM);
    cudaFuncSetAttribute(gemm_mma32, cudaFuncAttributeMaxDynamicSharedMemorySize, MMA1_SMEM);

    dim3 gs(256, 16);                 // split_x / mma_reduce_split: (k/32, n/32)
    dim3 gt(W2C / 128, Nn / 128, KCH);// layer-2 gemm: (4 N, 64 M, 4 kc)
    dim3 g1(Nn / 128, KC1);           // layer-1 gemm: (64 M, 8 kc)
    int  gr1 = (Nn * W1C / 4) / 256;

    convert_a3<<<(size_t)Nn * Nn / 4 / 256, 256>>>(a);
    pack_x_kernel<<<(Nn * W1C) / 256, 256>>>(x);

    // Layer 1: Chebyshev on [8192,32] via fp16 2-seg tensor path
    split_t<<<256, 256>>>(0);
    gemm_mma32<<<g1, 256, MMA1_SMEM>>>();
    w32_reduce8<<<gr1, 256>>>(-1, 1, 1.0f, 0.0f);               // T1
    split_t<<<256, 256>>>(1);
    gemm_mma32<<<g1, 256, MMA1_SMEM>>>();
    w32_reduce8<<<gr1, 256>>>(0, 2, 2.0f, -1.0f);               // T2
    split_t<<<256, 256>>>(2);
    gemm_mma32<<<g1, 256, MMA1_SMEM>>>();
    w32_reduce8<<<gr1, 256>>>(1, 3, 2.0f, -1.0f);               // T3
    split_t<<<256, 256>>>(3);
    gemm_mma32<<<g1, 256, MMA1_SMEM>>>();
    w32_reduce8<<<gr1, 256>>>(2, 4, 2.0f, -1.0f);               // T4
    combine1_kernel<<<(Nn * W2C) / 256, 256>>>(w1, b1);         // g_U[0] = H1

    // Layer 2: fp16 2-seg tensor path, split-K x4, fused reduce+split
    split_x<<<gs, 256>>>(0);
    gemm_mma<<<gt, 128, MMA_SMEM>>>();
    mma_reduce_split<<<gs, 256>>>(-1, 1, 1.0f, 0.0f, 1);        // U1 (+X3t)
    gemm_mma<<<gt, 128, MMA_SMEM>>>();
    mma_reduce_split<<<gs, 256>>>(0, 2, 2.0f, -1.0f, 1);        // U2 (+X3t)
    gemm_mma<<<gt, 128, MMA_SMEM>>>();
    mma_reduce_split<<<gs, 256>>>(1, 3, 2.0f, -1.0f, 1);        // U3 (+X3t)
    gemm_mma<<<gt, 128, MMA_SMEM>>>();
    mma_reduce_split<<<gs, 256>>>(2, 4, 2.0f, -1.0f, 0);        // U4
    combine2_kernel<<<(Nn * W2C) / 256, 256>>>(w2, b2);         // g_h

    // FC head
    fc1_partial<<<(Nn * F2) / FC1_J, 256>>>(fw1);
    fc1_reduce<<<(Bb * M1) / 256, 256>>>(fb1);
    fc2_kernel<<<(Bb * M2) / 256, 256>>>(fw2, fb2);
    fc3_kernel<<<1, 32>>>(fw3, fb3, out);
}

// round 17
// speedup vs baseline: 1.3176x; 1.3176x over previous
#include <cuda_runtime.h>
#include <cuda_fp16.h>
#include <cstdint>
#include <math.h>

#define Bb    16
#define Nn    8192
#define F1    32
#define F2    32
#define KORD  5
#define M1    512
#define M2    128
#define W1C   32
#define W2C   512

#define K2      16384       // A storage K: [Ah | Al] fp16
#define KB2     8192        // X/T storage K: [Xh] fp16
#define BKB     64          // fp16 per k-stage (128B rows -> SW128)
#define MSTAGES 3
#define NKI     256         // 2*8192/64 logical k-stages (AhXh + AlXh)
#define KCH     4           // layer-2 split-K chunks (R14-best)
#define LKI     (NKI / KCH) // 64 = 21*3 + 1
#define KC1     8           // layer-1 split-K chunks
#define LKI1    (NKI / KC1) // 32

// ---------------- scratch ---------------------------------------------------
__device__ __half g_A3[(size_t)Nn * K2];
__device__ __half g_X3t[(size_t)W2C * KB2];
__device__ __half g_T3t[(size_t)W1C * KB2];
__device__ float g_T[5][Nn * W1C];
__device__ float g_Tp[KC1][Nn * W1C];
__device__ float g_U[5][(size_t)Nn * W2C];
__device__ float g_Up[KCH][(size_t)Nn * W2C];
__device__ float g_h[(size_t)Bb * Nn * F2];
__device__ float g_p[512 * Bb * M1];
__device__ float g_fc1[Bb * M1];
__device__ float g_fc2[Bb * M2];

// ---------------- PTX helpers (compute_103 BASELINE only) ------------------
__device__ __forceinline__ uint32_t smem_u32(const void* p) {
    uint32_t a;
    asm("{ .reg .u64 t; cvta.to.shared.u64 t, %1; cvt.u32.u64 %0, t; }" : "=r"(a) : "l"(p));
    return a;
}
#define CP_ASYNC16(dst, src) \
    asm volatile("cp.async.cg.shared.global [%0], [%1], 16;" :: "r"(dst), "l"(src) : "memory")
#define CP_COMMIT() asm volatile("cp.async.commit_group;" ::: "memory")
#define CP_WAIT1()  asm volatile("cp.async.wait_group 1;" ::: "memory")
#define LDSM4(r0, r1, r2, r3, addr) \
    asm volatile("ldmatrix.sync.aligned.m8n8.x4.shared.b16 {%0,%1,%2,%3}, [%4];" \
        : "=r"(r0), "=r"(r1), "=r"(r2), "=r"(r3) : "r"(addr))
#define MMA16816(d, a, b0, b1) \
    asm volatile("mma.sync.aligned.m16n8k16.row.col.f32.f16.f16.f32 " \
        "{%0,%1,%2,%3}, {%4,%5,%6,%7}, {%8,%9}, {%0,%1,%2,%3};" \
        : "+f"((d)[0]), "+f"((d)[1]), "+f"((d)[2]), "+f"((d)[3]) \
        : "r"((a)[0]), "r"((a)[1]), "r"((a)[2]), "r"((a)[3]), "r"(b0), "r"(b1))
#define SWZ(o) ((o) ^ (((o) >> 3) & 0x70u))

// k-stage j in [0,256): A chunk = j (Ah j<128 | Al j>=128); X chunk = j&127
__device__ __forceinline__ int mapA(int j) { return j; }
__device__ __forceinline__ int mapB(int j) { return j & 127; }

// ---------------- A split: A3 = [fp16(A) | fp16(A-Ah)] ---------------------
__global__ __launch_bounds__(256) void convert_a3(const float* __restrict__ A) {
    size_t idx = ((size_t)blockIdx.x * 256 + threadIdx.x) * 4;
    float4 v = *(const float4*)(A + idx);
    int n = (int)(idx >> 13);
    int m = (int)(idx & 8191);
    float f[4] = {v.x, v.y, v.z, v.w};
    __half h0 = __float2half_rn(f[0]), h1 = __float2half_rn(f[1]);
    __half h2 = __float2half_rn(f[2]), h3 = __float2half_rn(f[3]);
    __half l0 = __float2half_rn(f[0] - __half2float(h0));
    __half l1 = __float2half_rn(f[1] - __half2float(h1));
    __half l2 = __float2half_rn(f[2] - __half2float(h2));
    __half l3 = __float2half_rn(f[3] - __half2float(h3));
    size_t b = (size_t)n * K2 + m;
    *(__half2*)(g_A3 + b)            = __halves2half2(h0, h1);
    *(__half2*)(g_A3 + b + 2)        = __halves2half2(h2, h3);
    *(__half2*)(g_A3 + b + 8192)     = __halves2half2(l0, l1);
    *(__half2*)(g_A3 + b + 8192 + 2) = __halves2half2(l2, l3);
}

// ---------------- pack x[B,N,2] -> T0[N,32] --------------------------------
__global__ void pack_x_kernel(const float* __restrict__ x) {
    int idx = blockIdx.x * blockDim.x + threadIdx.x;
    if (idx >= Nn * W1C) return;
    int q = idx & 31, n = idx >> 5;
    g_T[0][idx] = x[((size_t)(q >> 1) * Nn + n) * 2 + (q & 1)];
}

// ---------------- T rounding+transpose: T[in][N,32] -> T3t[32, KB2] --------
// (standalone use: T0 only; later steps fused into w32_reduce8_split)
__global__ __launch_bounds__(256) void split_t(int in_i) {
    __shared__ float t[32][33];
    const float* __restrict__ T = g_T[in_i];
    int tx = threadIdx.x & 31, ty = threadIdx.x >> 5;
    int k0 = blockIdx.x * 32;
    #pragma unroll
    for (int r = ty; r < 32; r += 8)
        t[r][tx] = T[(k0 + r) * W1C + tx];
    __syncthreads();
    #pragma unroll
    for (int r = ty; r < 32; r += 8)
        g_T3t[(size_t)r * KB2 + k0 + tx] = __float2half_rn(t[tx][r]);
}

// ---------------- X rounding+transpose (H1 only) ---------------------------
__global__ __launch_bounds__(256) void split_x(int in_i) {
    __shared__ float t[32][33];
    const float* __restrict__ U = g_U[in_i];
    int tx = threadIdx.x & 31, ty = threadIdx.x >> 5;
    int k0 = blockIdx.x * 32, n0 = blockIdx.y * 32;
    #pragma unroll
    for (int r = ty; r < 32; r += 8)
        t[r][tx] = U[(size_t)(k0 + r) * W2C + n0 + tx];
    __syncthreads();
    #pragma unroll
    for (int r = ty; r < 32; r += 8)
        g_X3t[(size_t)(n0 + r) * KB2 + k0 + tx] = __float2half_rn(t[tx][r]);
}

// ---------------- layer-1 tensor GEMM: partial(A3@T3t^T) -> g_Tp[kc] -------
// Tile 128x32, BK=64, 8 warps (4M x 2N), warp tile 32x16 = 2x2 m16n8k16.
#define SM1_STG 20480
__global__ __launch_bounds__(256, 3) void gemm_mma32() {
    extern __shared__ char dsm[];
    uint32_t tiles = (smem_u32(dsm) + 1023u) & ~1023u;
    const int tid  = threadIdx.x;
    const int lane = tid & 31, warp = tid >> 5;
    const int brow = blockIdx.x * 128;
    const int kc   = blockIdx.y;
    const int j0   = kc * LKI1;
    const int wm = (warp >> 1) * 32, wn = (warp & 1) * 16;

    const int lrow = tid >> 1;
    const int c16  = (tid & 1) << 2;
    uint32_t swA[4];
    #pragma unroll
    for (int q = 0; q < 4; q++)
        swA[q] = SWZ((uint32_t)lrow * 128u + (uint32_t)(c16 + q) * 16u);
    const uint32_t swB = SWZ((uint32_t)(tid >> 3) * 128u + (uint32_t)(tid & 7) * 16u);
    const __half* gA0 = g_A3  + (size_t)(brow + lrow) * K2 + (c16 << 3);
    const __half* gB0 = g_T3t + (size_t)(tid >> 3) * KB2 + (tid & 7) * 8;

    auto load_stage = [&](int s, int j) {
        uint32_t sA = tiles + (uint32_t)s * SM1_STG;
        uint32_t sB = sA + 16384u;
        const __half* pa = gA0 + mapA(j) * BKB;
        #pragma unroll
        for (int q = 0; q < 4; q++)
            CP_ASYNC16(sA + swA[q], pa + q * 8);
        CP_ASYNC16(sB + swB, gB0 + mapB(j) * BKB);
    };

    const int ar        = wm + (lane & 15);
    const uint32_t aMsk = (uint32_t)(ar & 7) << 4;
    const uint32_t aKhi = (uint32_t)((lane >> 4) << 4);
    const int br        = wn + (lane & 7) + ((lane >> 4) & 1) * 8;
    const uint32_t bMsk = (uint32_t)(lane & 7) << 4;
    const uint32_t bKhi = (uint32_t)(((lane >> 3) & 1) << 4);

    float acc[2][2][4];
    #pragma unroll
    for (int t = 0; t < 2; t++)
        #pragma unroll
        for (int u = 0; u < 2; u++)
            #pragma unroll
            for (int r = 0; r < 4; r++) acc[t][u][r] = 0.f;

    load_stage(0, j0); CP_COMMIT();
    load_stage(1, j0 + 1); CP_COMMIT();

    #define PROC1(s) do {                                                      \
        const int il = io + (s);                                               \
        CP_WAIT1();                                                            \
        __syncthreads();                                                       \
        if (il + 2 < LKI1) load_stage(((s) + 2) % MSTAGES, j0 + il + 2);       \
        CP_COMMIT();                                                           \
        const uint32_t As = tiles + (uint32_t)(s) * SM1_STG;                   \
        const uint32_t Bs = As + 16384u;                                       \
        _Pragma("unroll")                                                      \
        for (int ks = 0; ks < 4; ks++) {                                       \
            uint32_t ka = (uint32_t)(ks * 32) + aKhi;                          \
            uint32_t kb = (uint32_t)(ks * 32) + bKhi;                          \
            uint32_t a[2][4], b[4];                                            \
            _Pragma("unroll")                                                  \
            for (int t = 0; t < 2; t++)                                        \
                LDSM4(a[t][0], a[t][1], a[t][2], a[t][3],                      \
                      As + (uint32_t)(ar + t * 16) * 128u + (ka ^ aMsk));      \
            LDSM4(b[0], b[1], b[2], b[3],                                      \
                  Bs + (uint32_t)br * 128u + (kb ^ bMsk));                     \
            _Pragma("unroll")                                                  \
            for (int t = 0; t < 2; t++) {                                      \
                MMA16816(acc[t][0], a[t], b[0], b[1]);                         \
                MMA16816(acc[t][1], a[t], b[2], b[3]);                         \
            }                                                                  \
        }                                                                      \
    } while (0)

    for (int io = 0; io < 30; io += 3) {
        PROC1(0);
        PROC1(1);
        PROC1(2);
    }
    { const int io = 30; PROC1(0); }
    { const int io = 30; PROC1(1); }
    #undef PROC1

    float* Po = g_Tp[kc];
    #pragma unroll
    for (int t = 0; t < 2; t++) {
        int r0 = brow + wm + t * 16 + (lane >> 2);
        #pragma unroll
        for (int u = 0; u < 2; u++) {
            int c0 = wn + u * 8 + (lane & 3) * 2;
            size_t o0 = (size_t)r0 * W1C + c0;
            size_t o1 = o0 + 8 * W1C;
            Po[o0]     = acc[t][u][0];
            Po[o0 + 1] = acc[t][u][1];
            Po[o1]     = acc[t][u][2];
            Po[o1 + 1] = acc[t][u][3];
        }
    }
}

// ---------------- fused: T[out]=alpha*sum(8)+beta*T[prev]  (+T3t split) ----
// One block per 32 T-rows (k0). Same transpose trick as mma_reduce_split.
__global__ __launch_bounds__(256) void w32_reduce8_split(int prev_i, int out_i,
                                                         float alpha, float beta,
                                                         int do_split) {
    __shared__ float t[32][33];
    const int tid = threadIdx.x;
    const int k0 = blockIdx.x * 32;
    const int r  = tid >> 3;             // 0..31
    const int c4 = (tid & 7) << 2;       // 0,4,..,28

    size_t idx = (size_t)(k0 + r) * W1C + c4;
    float4 v = {0.f, 0.f, 0.f, 0.f};
    #pragma unroll
    for (int c = 0; c < KC1; c++) {
        float4 s = *(const float4*)(g_Tp[c] + idx);
        v.x += s.x; v.y += s.y; v.z += s.z; v.w += s.w;
    }
    v.x *= alpha; v.y *= alpha; v.z *= alpha; v.w *= alpha;
    if (prev_i >= 0) {
        float4 p = *(const float4*)(g_T[prev_i] + idx);
        v.x += beta * p.x; v.y += beta * p.y;
        v.z += beta * p.z; v.w += beta * p.w;
    }
    *(float4*)(g_T[out_i] + idx) = v;

    if (do_split) {
        t[r][c4 + 0] = v.x; t[r][c4 + 1] = v.y;
        t[r][c4 + 2] = v.z; t[r][c4 + 3] = v.w;
        __syncthreads();
        if (tid < 128) {
            int c  = tid >> 2;           // 0..31 (T col -> T3t row)
            int kk = (tid & 3) << 3;     // 0,8,16,24
            __half h[8];
            #pragma unroll
            for (int i = 0; i < 8; i++)
                h[i] = __float2half_rn(t[kk + i][c]);
            *(float4*)(g_T3t + (size_t)c * KB2 + k0 + kk) = *(float4*)h;
        }
    }
}

// ---------------- layer-2 tensor GEMM (R14-best): 8 warps, 64x32 warp tile -
__global__ __launch_bounds__(256, 2) void gemm_mma() {
    extern __shared__ char dsm[];
    uint32_t tiles = (smem_u32(dsm) + 1023u) & ~1023u;
    const int tid  = threadIdx.x;
    const int lane = tid & 31, warp = tid >> 5;
    const int bcol = blockIdx.x * 128, brow = blockIdx.y * 128;
    const int kc   = blockIdx.z;
    const int j0   = kc * LKI;
    const int wm = (warp >> 2) * 64, wn = (warp & 3) * 32;

    const int lrow = tid >> 1;
    const int c16  = (tid & 1) << 2;
    uint32_t swoff[4];
    #pragma unroll
    for (int q = 0; q < 4; q++)
        swoff[q] = SWZ((uint32_t)lrow * 128u + (uint32_t)(c16 + q) * 16u);
    const __half* gA0 = g_A3  + (size_t)(brow + lrow) * K2  + (c16 << 3);
    const __half* gB0 = g_X3t + (size_t)(bcol + lrow) * KB2 + (c16 << 3);

    auto load_stage = [&](int s, int j) {
        uint32_t sA = tiles + (uint32_t)s * 32768u;
        uint32_t sB = sA + 16384u;
        const __half* pa = gA0 + mapA(j) * BKB;
        const __half* pb = gB0 + mapB(j) * BKB;
        #pragma unroll
        for (int q = 0; q < 4; q++) {
            CP_ASYNC16(sA + swoff[q], pa + q * 8);
            CP_ASYNC16(sB + swoff[q], pb + q * 8);
        }
    };

    const int ar        = wm + (lane & 15);
    const uint32_t aMsk = (uint32_t)(ar & 7) << 4;
    const uint32_t aKhi = (uint32_t)((lane >> 4) << 4);
    const int br        = wn + (lane & 7) + ((lane >> 4) & 1) * 8;
    const uint32_t bMsk = (uint32_t)(lane & 7) << 4;
    const uint32_t bKhi = (uint32_t)(((lane >> 3) & 1) << 4);

    float acc[4][4][4];
    #pragma unroll
    for (int t = 0; t < 4; t++)
        #pragma unroll
        for (int u = 0; u < 4; u++)
            #pragma unroll
            for (int r = 0; r < 4; r++) acc[t][u][r] = 0.f;

    load_stage(0, j0); CP_COMMIT();
    load_stage(1, j0 + 1); CP_COMMIT();

    #define PROC_STAGE(s) do {                                                 \
        const int il = io + (s);                                               \
        CP_WAIT1();                                                            \
        __syncthreads();                                                       \
        if (il + 2 < LKI) load_stage(((s) + 2) % MSTAGES, j0 + il + 2);        \
        CP_COMMIT();                                                           \
        const uint32_t As = tiles + (uint32_t)(s) * 32768u;                    \
        const uint32_t Bs = As + 16384u;                                       \
        _Pragma("unroll")                                                      \
        for (int ks = 0; ks < 4; ks++) {                                       \
            uint32_t ka = (uint32_t)(ks * 32) + aKhi;                          \
            uint32_t kb = (uint32_t)(ks * 32) + bKhi;                          \
            uint32_t a[4][4], b[2][4];                                         \
            _Pragma("unroll")                                                  \
            for (int t = 0; t < 4; t++)                                        \
                LDSM4(a[t][0], a[t][1], a[t][2], a[t][3],                      \
                      As + (uint32_t)(ar + t * 16) * 128u + (ka ^ aMsk));      \
            _Pragma("unroll")                                                  \
            for (int p = 0; p < 2; p++)                                        \
                LDSM4(b[p][0], b[p][1], b[p][2], b[p][3],                      \
                      Bs + (uint32_t)(br + p * 16) * 128u + (kb ^ bMsk));      \
            _Pragma("unroll")                                                  \
            for (int t = 0; t < 4; t++) {                                      \
                _Pragma("unroll")                                              \
                for (int u = 0; u < 4; u++)                                    \
                    MMA16816(acc[t][u], a[t], b[u >> 1][(u & 1) * 2],          \
                                              b[u >> 1][(u & 1) * 2 + 1]);     \
            }                                                                  \
        }                                                                      \
    } while (0)

    // LKI = 64 = 21 triples (il 0..62) + il=63 (s=0)
    for (int io = 0; io < 63; io += 3) {
        PROC_STAGE(0);
        PROC_STAGE(1);
        PROC_STAGE(2);
    }
    { const int io = 63; PROC_STAGE(0); }
    #undef PROC_STAGE

    float* Po = g_Up[kc];
    #pragma unroll
    for (int t = 0; t < 4; t++) {
        int r0 = brow + wm + t * 16 + (lane >> 2);
        #pragma unroll
        for (int u = 0; u < 4; u++) {
            int c0 = bcol + wn + u * 8 + (lane & 3) * 2;
            size_t o0 = (size_t)r0 * W2C + c0;
            size_t o1 = o0 + 8 * W2C;
            Po[o0]     = acc[t][u][0];
            Po[o0 + 1] = acc[t][u][1];
            Po[o1]     = acc[t][u][2];
            Po[o1 + 1] = acc[t][u][3];
        }
    }
}

// ---------------- fused reduce (4 partials) + X split ----------------------
__global__ __launch_bounds__(256) void mma_reduce_split(int prev_i, int out_i,
                                                        float alpha, float beta,
                                                        int do_split) {
    __shared__ float t[32][33];
    const int tid = threadIdx.x;
    const int k0 = blockIdx.x * 32;      // U row (graph node) tile
    const int n0 = blockIdx.y * 32;      // U col tile
    const int r  = tid >> 3;             // 0..31
    const int c4 = (tid & 7) << 2;       // 0,4,..,28

    size_t idx = (size_t)(k0 + r) * W2C + n0 + c4;
    float4 s0 = *(const float4*)(g_Up[0] + idx);
    float4 s1 = *(const float4*)(g_Up[1] + idx);
    float4 s2 = *(const float4*)(g_Up[2] + idx);
    float4 s3 = *(const float4*)(g_Up[3] + idx);
    float4 v;
    v.x = alpha * (s0.x + s1.x + s2.x + s3.x);
    v.y = alpha * (s0.y + s1.y + s2.y + s3.y);
    v.z = alpha * (s0.z + s1.z + s2.z + s3.z);
    v.w = alpha * (s0.w + s1.w + s2.w + s3.w);
    if (prev_i >= 0) {
        float4 p = *(const float4*)(g_U[prev_i] + idx);
        v.x += beta * p.x; v.y += beta * p.y;
        v.z += beta * p.z; v.w += beta * p.w;
    }
    *(float4*)(g_U[out_i] + idx) = v;

    if (do_split) {
        t[r][c4 + 0] = v.x; t[r][c4 + 1] = v.y;
        t[r][c4 + 2] = v.z; t[r][c4 + 3] = v.w;
        __syncthreads();
        if (tid < 128) {
            int c  = tid >> 2;           // 0..31 (U col -> X3t row)
            int kk = (tid & 3) << 3;     // 0,8,16,24
            __half h[8];
            #pragma unroll
            for (int i = 0; i < 8; i++)
                h[i] = __float2half_rn(t[kk + i][c]);
            *(float4*)(g_X3t + (size_t)(n0 + c) * KB2 + k0 + kk) = *(float4*)h;
        }
    }
}

// ---------------- combines --------------------------------------------------
__global__ void combine1_kernel(const float* __restrict__ w1,
                                const float* __restrict__ b1) {
    int idx = blockIdx.x * blockDim.x + threadIdx.x;
    int c = idx & 31, b = (idx >> 5) & 15, n = idx >> 9;
    float v = b1[c];
    int tb = n * W1C + b * 2;
    #pragma unroll
    for (int k = 0; k < KORD; k++) {
        v = fmaf(g_T[k][tb + 0], w1[(k*2+0)*32 + c], v);
        v = fmaf(g_T[k][tb + 1], w1[(k*2+1)*32 + c], v);
    }
    g_U[0][(size_t)n * W2C + b * 32 + c] = fmaxf(v, 0.0f);
}

__global__ void combine2_kernel(const float* __restrict__ w2,
                                const float* __restrict__ b2) {
    int idx = blockIdx.x * blockDim.x + threadIdx.x;
    int c = idx & 31, b = (idx >> 5) & 15, n = idx >> 9;
    float v = b2[c];
    size_t ub = (size_t)n * W2C + b * 32;
    #pragma unroll
    for (int k = 0; k < KORD; k++)
        #pragma unroll
        for (int f = 0; f < F1; f++)
            v = fmaf(g_U[k][ub + f], w2[(k*F1 + f)*F2 + c], v);
    g_h[(size_t)b * (Nn * F2) + n * F2 + c] = fmaxf(v, 0.0f);
}

// ---------------- FC head ---------------------------------------------------
#define FC1_J 512
__global__ __launch_bounds__(256) void fc1_partial(const float* __restrict__ fw1) {
    __shared__ float hs[16][FC1_J];
    int tid = threadIdx.x;
    int j0  = blockIdx.x * FC1_J;
    for (int t = tid; t < 16 * FC1_J; t += 256)
        hs[t >> 9][t & (FC1_J - 1)] = g_h[(size_t)(t >> 9) * (Nn * F2) + j0 + (t & (FC1_J - 1))];
    __syncthreads();
    float acc0[16], acc1[16];
    #pragma unroll
    for (int b = 0; b < 16; b++) { acc0[b] = 0.f; acc1[b] = 0.f; }
    for (int jj = 0; jj < FC1_J; jj++) {
        float w0 = fw1[(size_t)(j0 + jj) * M1 + tid];
        float wA = fw1[(size_t)(j0 + jj) * M1 + tid + 256];
        #pragma unroll
        for (int b = 0; b < 16; b++) {
            float hv = hs[b][jj];
            acc0[b] = fmaf(hv, w0, acc0[b]);
            acc1[b] = fmaf(hv, wA, acc1[b]);
        }
    }
    size_t pb = (size_t)blockIdx.x * (16 * M1);
    #pragma unroll
    for (int b = 0; b < 16; b++) {
        g_p[pb + b * M1 + tid]       = acc0[b];
        g_p[pb + b * M1 + tid + 256] = acc1[b];
    }
}

__global__ void fc1_reduce(const float* __restrict__ fb1) {
    int idx = blockIdx.x * blockDim.x + threadIdx.x;
    float v = fb1[idx & (M1 - 1)];
    for (int ch = 0; ch < 512; ch++) v += g_p[(size_t)ch * (16 * M1) + idx];
    g_fc1[idx] = fmaxf(v, 0.0f);
}

__global__ void fc2_kernel(const float* __restrict__ fw2,
                           const float* __restrict__ fb2) {
    int idx = blockIdx.x * blockDim.x + threadIdx.x;
    int b = idx >> 7, m = idx & 127;
    float v = fb2[m];
    for (int j = 0; j < M1; j++)
        v = fmaf(g_fc1[b * M1 + j], fw2[j * M2 + m], v);
    g_fc2[idx] = fmaxf(v, 0.0f);
}

__global__ void fc3_kernel(const float* __restrict__ fw3,
                           const float* __restrict__ fb3,
                           float* __restrict__ out) {
    int b = threadIdx.x;
    if (b >= Bb) return;
    float l0 = fb3[0], l1 = fb3[1];
    for (int j = 0; j < M2; j++) {
        float h = g_fc2[b * M2 + j];
        l0 = fmaf(h, fw3[j * 2 + 0], l0);
        l1 = fmaf(h, fw3[j * 2 + 1], l1);
    }
    float mx = fmaxf(l0, l1);
    float e0 = expf(l0 - mx), e1 = expf(l1 - mx);
    float s = e0 + e1;
    out[b * 2 + 0] = e0 / s;
    out[b * 2 + 1] = e1 / s;
}

// ---------------- launcher -------------------------------------------------
#define MMA_SMEM  (MSTAGES * 32768 + 1024)
#define MMA1_SMEM (MSTAGES * SM1_STG + 1024)

extern "C" void kernel_launch(void* const* d_in, const int* in_sizes, int n_in,
                              void* d_out, int out_size) {
    const float* x   = (const float*)d_in[0];
    const float* a   = (const float*)d_in[1];
    const float* w1  = (const float*)d_in[2];
    const float* b1  = (const float*)d_in[3];
    const float* w2  = (const float*)d_in[4];
    const float* b2  = (const float*)d_in[5];
    const float* fw1 = (const float*)d_in[6];
    const float* fb1 = (const float*)d_in[7];
    const float* fw2 = (const float*)d_in[8];
    const float* fb2 = (const float*)d_in[9];
    const float* fw3 = (const float*)d_in[10];
    const float* fb3 = (const float*)d_in[11];
    float* out = (float*)d_out;

    cudaFuncSetAttribute(gemm_mma,   cudaFuncAttributeMaxDynamicSharedMemorySize, MMA_SMEM);
    cudaFuncSetAttribute(gemm_mma32, cudaFuncAttributeMaxDynamicSharedMemorySize, MMA1_SMEM);

    dim3 gs(256, 16);                 // split_x / mma_reduce_split: (k/32, n/32)
    dim3 gt(W2C / 128, Nn / 128, KCH);// layer-2 gemm: (4 N, 64 M, 4 kc)
    dim3 g1(Nn / 128, KC1);           // layer-1 gemm: (64 M, 8 kc)

    convert_a3<<<(size_t)Nn * Nn / 4 / 256, 256>>>(a);
    pack_x_kernel<<<(Nn * W1C) / 256, 256>>>(x);

    // Layer 1: fp16 2-seg tensor path; reduce fused with T3t split
    split_t<<<256, 256>>>(0);
    gemm_mma32<<<g1, 256, MMA1_SMEM>>>();
    w32_reduce8_split<<<256, 256>>>(-1, 1, 1.0f, 0.0f, 1);      // T1 (+T3t)
    gemm_mma32<<<g1, 256, MMA1_SMEM>>>();
    w32_reduce8_split<<<256, 256>>>(0, 2, 2.0f, -1.0f, 1);      // T2 (+T3t)
    gemm_mma32<<<g1, 256, MMA1_SMEM>>>();
    w32_reduce8_split<<<256, 256>>>(1, 3, 2.0f, -1.0f, 1);      // T3 (+T3t)
    gemm_mma32<<<g1, 256, MMA1_SMEM>>>();
    w32_reduce8_split<<<256, 256>>>(2, 4, 2.0f, -1.0f, 0);      // T4
    combine1_kernel<<<(Nn * W2C) / 256, 256>>>(w1, b1);         // g_U[0] = H1

    // Layer 2: fp16 2-seg tensor path, split-K x4, fused reduce+split
    split_x<<<gs, 256>>>(0);
    gemm_mma<<<gt, 256, MMA_SMEM>>>();
    mma_reduce_split<<<gs, 256>>>(-1, 1, 1.0f, 0.0f, 1);        // U1 (+X3t)
    gemm_mma<<<gt, 256, MMA_SMEM>>>();
    mma_reduce_split<<<gs, 256>>>(0, 2, 2.0f, -1.0f, 1);        // U2 (+X3t)
    gemm_mma<<<gt, 256, MMA_SMEM>>>();
    mma_reduce_split<<<gs, 256>>>(1, 3, 2.0f, -1.0f, 1);        // U3 (+X3t)
    gemm_mma<<<gt, 256, MMA_SMEM>>>();
    mma_reduce_split<<<gs, 256>>>(2, 4, 2.0f, -1.0f, 0);        // U4
    combine2_kernel<<<(Nn * W2C) / 256, 256>>>(w2, b2);         // g_h

    // FC head
    fc1_partial<<<(Nn * F2) / FC1_J, 256>>>(fw1);
    fc1_reduce<<<(Bb * M1) / 256, 256>>>(fb1);
    fc2_kernel<<<(Bb * M2) / 256, 256>>>(fw2, fb2);
    fc3_kernel<<<1, 32>>>(fw3, fb3, out);
}